// round 5
// baseline (speedup 1.0000x reference)
#include <cuda_runtime.h>
#include <math.h>

#define BB 2
#define SS 2048
#define DD 1024
#define HH 16
#define HD 64

#define NEG_INF (__int_as_float(0xff800000))

__device__ float g_q[BB*HH*SS*HD];
__device__ float g_k[BB*HH*SS*HD];
__device__ float g_v[BB*HH*SS*HD];
__device__ float g_wv[(size_t)BB*SS*DD];

// ---------------------------------------------------------------------------
// C = (A @ W^T + bias) * scale
// A: [M, 1024] row-major, W: [1024, 1024] row-major (torch Linear weight)
// HEAD=true: write into [B,H,S,hd] layout; else row-major [M,1024].
// Tiles: BM=BN=64, BK=16, 256 threads, 4x4 microtile per thread.
// ---------------------------------------------------------------------------
template<bool HEAD>
__global__ __launch_bounds__(256)
void sgemm_kernel(const float* __restrict__ A, const float* __restrict__ W,
                  const float* __restrict__ bias, float scale,
                  float* __restrict__ C)
{
    __shared__ float As[16][68];
    __shared__ float Bs[16][68];
    const int tid = threadIdx.x;
    const int ty = tid >> 4, tx = tid & 15;
    const int m0 = blockIdx.y * 64, n0 = blockIdx.x * 64;
    const int lr = tid >> 2;          // 0..63
    const int lc = (tid & 3) << 2;    // 0,4,8,12

    float acc[4][4] = {};
    const float* Ap = A + (size_t)(m0 + lr) * DD + lc;
    const float* Wp = W + (size_t)(n0 + lr) * DD + lc;

    for (int kt = 0; kt < DD; kt += 16) {
        float4 av = *(const float4*)(Ap + kt);
        float4 wv = *(const float4*)(Wp + kt);
        __syncthreads();
        As[lc+0][lr] = av.x; As[lc+1][lr] = av.y; As[lc+2][lr] = av.z; As[lc+3][lr] = av.w;
        Bs[lc+0][lr] = wv.x; Bs[lc+1][lr] = wv.y; Bs[lc+2][lr] = wv.z; Bs[lc+3][lr] = wv.w;
        __syncthreads();
        #pragma unroll
        for (int k = 0; k < 16; ++k) {
            float4 a4 = *(const float4*)&As[k][ty << 2];
            float4 b4 = *(const float4*)&Bs[k][tx << 2];
            float ar[4] = {a4.x, a4.y, a4.z, a4.w};
            float br[4] = {b4.x, b4.y, b4.z, b4.w};
            #pragma unroll
            for (int i = 0; i < 4; ++i)
                #pragma unroll
                for (int j = 0; j < 4; ++j)
                    acc[i][j] = fmaf(ar[i], br[j], acc[i][j]);
        }
    }

    const int c0 = n0 + (tx << 2);
    float b0 = bias ? bias[c0+0] : 0.f;
    float b1 = bias ? bias[c0+1] : 0.f;
    float b2 = bias ? bias[c0+2] : 0.f;
    float b3 = bias ? bias[c0+3] : 0.f;
    #pragma unroll
    for (int i = 0; i < 4; ++i) {
        int r = m0 + (ty << 2) + i;
        float4 v;
        v.x = (acc[i][0] + b0) * scale;
        v.y = (acc[i][1] + b1) * scale;
        v.z = (acc[i][2] + b2) * scale;
        v.w = (acc[i][3] + b3) * scale;
        if (HEAD) {
            int bb = r >> 11;          // r / S
            int s  = r & (SS - 1);
            int h  = c0 >> 6;          // c / hd
            int d  = c0 & 63;
            *(float4*)(C + (((size_t)(bb * HH + h)) * SS + s) * HD + d) = v;
        } else {
            *(float4*)(C + (size_t)r * DD + c0) = v;
        }
    }
}

// ---------------------------------------------------------------------------
// RoPE in-place on q and k ([B,H,S,hd] layout). One thread handles the pair
// (j, j+32) of one row.
// ---------------------------------------------------------------------------
__global__ void rope_kernel(float* __restrict__ q, float* __restrict__ k,
                            const int* __restrict__ pos)
{
    int idx = blockIdx.x * blockDim.x + threadIdx.x;
    if (idx >= BB * HH * SS * 32) return;
    int j  = idx & 31;
    int s  = (idx >> 5) & (SS - 1);
    int bh = idx >> 16;                  // 32*2048 = 65536 per (b,h)
    int b  = bh >> 4;

    int p = pos[b * SS + s];
    // inv_freq = 10000^(-2j/64)
    float inv = expf(-(float)(2 * j) * (9.210340371976184f / 64.f));
    float ang = (float)p * inv;
    float sn, cs;
    sincosf(ang, &sn, &cs);

    size_t base = (size_t)bh * SS * HD + (size_t)s * HD + j;
    float q1 = q[base], q2 = q[base + 32];
    q[base]      = q1 * cs - q2 * sn;
    q[base + 32] = q2 * cs + q1 * sn;
    float k1 = k[base], k2 = k[base + 32];
    k[base]      = k1 * cs - k2 * sn;
    k[base + 32] = k2 * cs + k1 * sn;
}

// ---------------------------------------------------------------------------
// Flash-style attention per (b,h): 64-query blocks, 64-key tiles, online
// softmax. Writes raw logits (post-mask) tiles to qk_out and the attention
// output into wv_out in [B,S,D] layout.
// Dynamic smem: Qst[64][68] (d-major) | KPs[64][68] (K d-major, reused as
// P row-major) | Vs[64][68] | red[64][16] | mki[64]
// ---------------------------------------------------------------------------
#define ATTN_SMEM ((3*64*68 + 64*16) * 4 + 64 * 4)

__global__ __launch_bounds__(256, 2)
void attn_kernel(const float* __restrict__ gq, const float* __restrict__ gk,
                 const float* __restrict__ gv, const int* __restrict__ mask,
                 float* __restrict__ qk_out, float* __restrict__ wv_out)
{
    extern __shared__ float sm[];
    float* Qst = sm;
    float* KPs = sm + 64 * 68;
    float* Vs  = sm + 2 * 64 * 68;
    float* red = sm + 3 * 64 * 68;
    int*   mki = (int*)(red + 64 * 16);

    const int tid = threadIdx.x;
    const int ty = tid >> 4, tx = tid & 15;
    const int qb = blockIdx.x;
    const int bh = blockIdx.y;
    const int b = bh >> 4, h = bh & 15;

    const float* qp = gq + (size_t)bh * SS * HD + (size_t)qb * 64 * HD;
    const float* kp = gk + (size_t)bh * SS * HD;
    const float* vp = gv + (size_t)bh * SS * HD;
    const int*   mp = mask + b * SS;
    float* qkp = qk_out ? qk_out + (size_t)bh * SS * SS + (size_t)qb * 64 * SS
                        : (float*)0;

    // load Q tile transposed: Qst[d][row]
    #pragma unroll
    for (int it = 0; it < 4; ++it) {
        int t4 = tid + it * 256;
        int r = t4 >> 4, c4 = (t4 & 15) << 2;
        float4 v = *(const float4*)(qp + r * HD + c4);
        Qst[(c4+0)*68 + r] = v.x;
        Qst[(c4+1)*68 + r] = v.y;
        Qst[(c4+2)*68 + r] = v.z;
        Qst[(c4+3)*68 + r] = v.w;
    }

    float o[4][4] = {};
    float mI[4], lI[4];
    #pragma unroll
    for (int i = 0; i < 4; ++i) { mI[i] = NEG_INF; lI[i] = 0.f; }

    for (int jt = 0; jt < SS / 64; ++jt) {
        __syncthreads();   // protect KPs/Vs reads of previous iteration
        const float* kb = kp + (size_t)jt * 64 * HD;
        const float* vb = vp + (size_t)jt * 64 * HD;
        #pragma unroll
        for (int it = 0; it < 4; ++it) {
            int t4 = tid + it * 256;
            int r = t4 >> 4, c4 = (t4 & 15) << 2;
            float4 kv = *(const float4*)(kb + r * HD + c4);
            KPs[(c4+0)*68 + r] = kv.x;
            KPs[(c4+1)*68 + r] = kv.y;
            KPs[(c4+2)*68 + r] = kv.z;
            KPs[(c4+3)*68 + r] = kv.w;
            *(float4*)(Vs + r * 68 + c4) = *(const float4*)(vb + r * HD + c4);
        }
        if (tid < 64) mki[tid] = mp[jt * 64 + tid];
        __syncthreads();

        // S tile = Q @ K^T  (both pre-scaled by hd^-0.25)
        float acc[4][4] = {};
        #pragma unroll 16
        for (int d = 0; d < 64; ++d) {
            float4 a4 = *(const float4*)(Qst + d * 68 + (ty << 2));
            float4 b4 = *(const float4*)(KPs + d * 68 + (tx << 2));
            float ar[4] = {a4.x, a4.y, a4.z, a4.w};
            float br[4] = {b4.x, b4.y, b4.z, b4.w};
            #pragma unroll
            for (int i = 0; i < 4; ++i)
                #pragma unroll
                for (int j = 0; j < 4; ++j)
                    acc[i][j] = fmaf(ar[i], br[j], acc[i][j]);
        }

        int km[4];
        #pragma unroll
        for (int j = 0; j < 4; ++j) km[j] = mki[(tx << 2) + j];

        float sv[4][4], tmax[4];
        #pragma unroll
        for (int i = 0; i < 4; ++i) {
            tmax[i] = NEG_INF;
            #pragma unroll
            for (int j = 0; j < 4; ++j) {
                float v = km[j] ? acc[i][j] : NEG_INF;
                sv[i][j] = v;
                tmax[i] = fmaxf(tmax[i], v);
            }
        }

        // write raw (masked) logits tile
        if (qkp) {
            #pragma unroll
            for (int i = 0; i < 4; ++i) {
                float4 w = {sv[i][0], sv[i][1], sv[i][2], sv[i][3]};
                *(float4*)(qkp + (size_t)((ty << 2) + i) * SS + jt * 64 + (tx << 2)) = w;
            }
        }

        #pragma unroll
        for (int i = 0; i < 4; ++i) red[((ty << 2) + i) * 16 + tx] = tmax[i];
        __syncthreads();   // acc done for all -> KPs free; red(max) ready

        float mnew[4], fct[4];
        #pragma unroll
        for (int i = 0; i < 4; ++i) {
            float mx = mI[i];
            const float* rr = red + ((ty << 2) + i) * 16;
            #pragma unroll
            for (int t = 0; t < 16; ++t) mx = fmaxf(mx, rr[t]);
            mnew[i] = mx;
            fct[i] = (mx == NEG_INF) ? 1.f : __expf(mI[i] - mx);
        }
        __syncthreads();   // everyone done reading red(max)

        float psum[4] = {0.f, 0.f, 0.f, 0.f};
        #pragma unroll
        for (int i = 0; i < 4; ++i) {
            bool dead = (mnew[i] == NEG_INF);
            #pragma unroll
            for (int j = 0; j < 4; ++j) {
                float p = dead ? 0.f : __expf(sv[i][j] - mnew[i]);
                psum[i] += p;
                KPs[((ty << 2) + i) * 68 + (tx << 2) + j] = p;  // P row-major
            }
            red[((ty << 2) + i) * 16 + tx] = psum[i];
            #pragma unroll
            for (int j = 0; j < 4; ++j) o[i][j] *= fct[i];
        }
        __syncthreads();   // P and red(sum) ready

        #pragma unroll
        for (int i = 0; i < 4; ++i) {
            float s = 0.f;
            const float* rr = red + ((ty << 2) + i) * 16;
            #pragma unroll
            for (int t = 0; t < 16; ++t) s += rr[t];
            lI[i] = lI[i] * fct[i] + s;
            mI[i] = mnew[i];
        }

        // O += P @ V
        #pragma unroll 8
        for (int kk = 0; kk < 64; ++kk) {
            float4 v4 = *(const float4*)(Vs + kk * 68 + (tx << 2));
            float vr[4] = {v4.x, v4.y, v4.z, v4.w};
            #pragma unroll
            for (int i = 0; i < 4; ++i) {
                float pv = KPs[((ty << 2) + i) * 68 + kk];
                #pragma unroll
                for (int j = 0; j < 4; ++j)
                    o[i][j] = fmaf(pv, vr[j], o[i][j]);
            }
        }
    }

    // epilogue: normalize and write to [B,S,D] layout
    #pragma unroll
    for (int i = 0; i < 4; ++i) {
        float inv = (lI[i] > 0.f) ? 1.f / lI[i] : 0.f;
        int s = qb * 64 + (ty << 2) + i;
        float4 w = {o[i][0]*inv, o[i][1]*inv, o[i][2]*inv, o[i][3]*inv};
        *(float4*)(wv_out + ((size_t)b * SS + s) * DD + h * HD + (tx << 2)) = w;
    }
}

// ---------------------------------------------------------------------------
extern "C" void kernel_launch(void* const* d_in, const int* in_sizes, int n_in,
                              void* d_out, int out_size)
{
    const float* x    = (const float*)d_in[0];
    const int*   mask = (const int*)d_in[1];
    const int*   pos  = (const int*)d_in[2];
    // d_in[3] = n_head (16, hardcoded)
    const float* Wq = (const float*)d_in[4];
    const float* bq = (const float*)d_in[5];
    const float* Wk = (const float*)d_in[6];
    const float* Wv = (const float*)d_in[7];
    const float* bv = (const float*)d_in[8];
    const float* Wo = (const float*)d_in[9];
    const float* bo = (const float*)d_in[10];
    float* out = (float*)d_out;

    float *q_, *k_, *v_, *wv_;
    cudaGetSymbolAddress((void**)&q_,  g_q);
    cudaGetSymbolAddress((void**)&k_,  g_k);
    cudaGetSymbolAddress((void**)&v_,  g_v);
    cudaGetSymbolAddress((void**)&wv_, g_wv);

    const long long OUTE = (long long)BB * SS * DD;
    const long long QKE  = (long long)BB * HH * SS * SS;
    float* qkp = ((long long)out_size >= OUTE + QKE) ? out + OUTE : (float*)0;

    const float SC = 0.35355339059327373f;   // 64^-0.25

    dim3 blk(256);
    dim3 g1(DD / 64, (BB * SS) / 64);
    sgemm_kernel<true><<<g1, blk>>>(x, Wq, bq, SC, q_);
    sgemm_kernel<true><<<g1, blk>>>(x, Wk, (const float*)0, SC, k_);
    sgemm_kernel<true><<<g1, blk>>>(x, Wv, bv, 1.f, v_);

    rope_kernel<<<(BB * HH * SS * 32) / 256, 256>>>(q_, k_, pos);

    cudaFuncSetAttribute(attn_kernel,
                         cudaFuncAttributeMaxDynamicSharedMemorySize, ATTN_SMEM);
    attn_kernel<<<dim3(SS / 64, BB * HH), blk, ATTN_SMEM>>>(q_, k_, v_, mask, qkp, wv_);

    sgemm_kernel<false><<<g1, blk>>>(wv_, Wo, bo, 1.f, out);
}

// round 10
// speedup vs baseline: 2.2990x; 2.2990x over previous
#include <cuda_runtime.h>
#include <cuda_bf16.h>
#include <stdint.h>
#include <math.h>

#define BB 2
#define SS 2048
#define DD 1024
#define HH 16
#define HD 64
#define NEG_INF (__int_as_float(0xff800000))

// ---------------- device scratch ----------------
__device__ __nv_bfloat16 xh_d[BB*SS*DD], xl_d[BB*SS*DD];
__device__ __nv_bfloat16 Wqh_d[DD*DD], Wql_d[DD*DD];
__device__ __nv_bfloat16 Wkh_d[DD*DD], Wkl_d[DD*DD];
__device__ __nv_bfloat16 Wvh_d[DD*DD], Wvl_d[DD*DD];
__device__ __nv_bfloat16 Woh_d[DD*DD], Wol_d[DD*DD];
__device__ float qf_d[BB*HH*SS*HD], kf_d[BB*HH*SS*HD], vf_d[BB*HH*SS*HD];
__device__ __nv_bfloat16 qh_d[BB*HH*SS*HD], ql_d[BB*HH*SS*HD];
__device__ __nv_bfloat16 kh_d[BB*HH*SS*HD], kl_d[BB*HH*SS*HD];
__device__ __nv_bfloat16 vth_d[BB*HH*SS*HD], vtl_d[BB*HH*SS*HD];
__device__ __nv_bfloat16 oh_d[BB*SS*DD], ol_d[BB*SS*DD];

// ---------------- helpers ----------------
__device__ __forceinline__ uint32_t smem_u32(const void* p) {
    uint32_t a;
    asm("{ .reg .u64 t; cvta.to.shared.u64 t, %1; cvt.u32.u64 %0, t; }" : "=r"(a) : "l"(p));
    return a;
}
#define SWZ(x) ((x) ^ (((x) >> 3) & 0x70))

__device__ __forceinline__ void ldm4(uint32_t r[4], uint32_t a) {
    asm volatile("ldmatrix.sync.aligned.m8n8.x4.shared.b16 {%0,%1,%2,%3}, [%4];"
        : "=r"(r[0]), "=r"(r[1]), "=r"(r[2]), "=r"(r[3]) : "r"(a));
}
__device__ __forceinline__ void mma_bf16(float* c, const uint32_t* a, const uint32_t* b) {
    asm volatile("mma.sync.aligned.m16n8k16.row.col.f32.bf16.bf16.f32 "
        "{%0,%1,%2,%3}, {%4,%5,%6,%7}, {%8,%9}, {%0,%1,%2,%3};"
        : "+f"(c[0]), "+f"(c[1]), "+f"(c[2]), "+f"(c[3])
        : "r"(a[0]), "r"(a[1]), "r"(a[2]), "r"(a[3]), "r"(b[0]), "r"(b[1]));
}
__device__ __forceinline__ uint32_t pk2(float a, float b) {
    __nv_bfloat162 t = __floats2bfloat162_rn(a, b);
    return *(uint32_t*)&t;
}
__device__ __forceinline__ float bfh(float v) {           // value of bf16 hi part
    return __bfloat162float(__float2bfloat16_rn(v));
}
__device__ __forceinline__ void split1(float v, __nv_bfloat16& h, __nv_bfloat16& l) {
    h = __float2bfloat16_rn(v);
    l = __float2bfloat16_rn(v - __bfloat162float(h));
}

// ---------------- split kernel ----------------
__global__ void split_kernel(const float* __restrict__ in,
                             __nv_bfloat16* __restrict__ oh,
                             __nv_bfloat16* __restrict__ ol, int n4) {
    int i = blockIdx.x * blockDim.x + threadIdx.x;
    if (i >= n4) return;
    float4 v = ((const float4*)in)[i];
    uint2 hv, lv;
    hv.x = pk2(v.x, v.y); hv.y = pk2(v.z, v.w);
    lv.x = pk2(v.x - bfh(v.x), v.y - bfh(v.y));
    lv.y = pk2(v.z - bfh(v.z), v.w - bfh(v.w));
    ((uint2*)oh)[i] = hv;
    ((uint2*)ol)[i] = lv;
}

// ---------------- split-bf16 HMMA GEMM ----------------
// C[m,n] = (sum_k A[m,k]*W[n,k] + bias[n]) * scale ; M=4096 K=N=1024
// tile 128x128, K-chunk 64, 256 thr, 8 warps (2m x 4n), warp tile 64x32.
#define G_AH 0
#define G_AL 16384
#define G_BH 32768
#define G_BL 49152
#define G_SMEM 65536

template<bool HEAD>
__global__ __launch_bounds__(256)
void bgemm(const __nv_bfloat16* __restrict__ Ah, const __nv_bfloat16* __restrict__ Al,
           const __nv_bfloat16* __restrict__ Bh, const __nv_bfloat16* __restrict__ Bl,
           const float* __restrict__ bias, float scale, float* __restrict__ C)
{
    extern __shared__ char sm[];
    const uint32_t sb = smem_u32(sm);
    const int tid = threadIdx.x, wid = tid >> 5, l = tid & 31;
    const int wm = wid & 1, wn = wid >> 1;
    const int m0 = blockIdx.y * 128, n0 = blockIdx.x * 128;

    float acc[4][4][4] = {};

    for (int c = 0; c < 16; ++c) {
        const int kt = c * 64;
        if (c > 0) __syncthreads();
        #pragma unroll
        for (int t = 0; t < 4; ++t) {
            int e = tid + t * 256;
            int row = e >> 3, u = e & 7;
            uint32_t dst = SWZ((uint32_t)(row * 128 + u * 16));
            *(uint4*)(sm + G_AH + dst) = *(const uint4*)(Ah + (size_t)(m0 + row) * DD + kt + u * 8);
            *(uint4*)(sm + G_AL + dst) = *(const uint4*)(Al + (size_t)(m0 + row) * DD + kt + u * 8);
            *(uint4*)(sm + G_BH + dst) = *(const uint4*)(Bh + (size_t)(n0 + row) * DD + kt + u * 8);
            *(uint4*)(sm + G_BL + dst) = *(const uint4*)(Bl + (size_t)(n0 + row) * DD + kt + u * 8);
        }
        __syncthreads();
        #pragma unroll
        for (int ks = 0; ks < 4; ++ks) {
            uint32_t bh4[2][4], bl4[2][4];
            #pragma unroll
            for (int np = 0; np < 2; ++np) {
                int row = wn * 32 + np * 16 + ((l >> 4) & 1) * 8 + (l & 7);
                uint32_t off = SWZ((uint32_t)(row * 128 + ks * 32 + ((l >> 3) & 1) * 16));
                ldm4(bh4[np], sb + G_BH + off);
                ldm4(bl4[np], sb + G_BL + off);
            }
            #pragma unroll
            for (int mt = 0; mt < 4; ++mt) {
                int row = wm * 64 + mt * 16 + (l & 7) + ((l >> 3) & 1) * 8;
                uint32_t off = SWZ((uint32_t)(row * 128 + ks * 32 + ((l >> 4) & 1) * 16));
                uint32_t ah4[4], al4[4];
                ldm4(ah4, sb + G_AH + off);
                ldm4(al4, sb + G_AL + off);
                #pragma unroll
                for (int nt = 0; nt < 4; ++nt) {
                    const uint32_t* bh = &bh4[nt >> 1][(nt & 1) * 2];
                    const uint32_t* bl = &bl4[nt >> 1][(nt & 1) * 2];
                    mma_bf16(acc[mt][nt], ah4, bh);
                    mma_bf16(acc[mt][nt], al4, bh);
                    mma_bf16(acc[mt][nt], ah4, bl);
                }
            }
        }
    }

    #pragma unroll
    for (int mt = 0; mt < 4; ++mt) {
        #pragma unroll
        for (int nt = 0; nt < 4; ++nt) {
            const float* cc = acc[mt][nt];
            int col = n0 + wn * 32 + nt * 8 + 2 * (l & 3);
            float b0 = bias ? bias[col] : 0.f;
            float b1 = bias ? bias[col + 1] : 0.f;
            int r0 = m0 + wm * 64 + mt * 16 + (l >> 2);
            #pragma unroll
            for (int hh = 0; hh < 2; ++hh) {
                int r = r0 + hh * 8;
                float2 w = {(cc[hh*2] + b0) * scale, (cc[hh*2+1] + b1) * scale};
                if (HEAD) {
                    int bb = r >> 11, s = r & (SS - 1);
                    int h = col >> 6, d = col & 63;
                    *(float2*)(C + (((size_t)(bb * HH + h)) * SS + s) * HD + d) = w;
                } else {
                    *(float2*)(C + (size_t)r * DD + col) = w;
                }
            }
        }
    }
}

// ---------------- RoPE + split ----------------
__global__ void rope_kernel(const float* __restrict__ q, const float* __restrict__ k,
                            const int* __restrict__ pos,
                            __nv_bfloat16* __restrict__ qh, __nv_bfloat16* __restrict__ ql,
                            __nv_bfloat16* __restrict__ kh, __nv_bfloat16* __restrict__ kl)
{
    int idx = blockIdx.x * blockDim.x + threadIdx.x;
    if (idx >= BB * HH * SS * 32) return;
    int j = idx & 31;
    int s = (idx >> 5) & (SS - 1);
    int bh = idx >> 16;
    int b = bh >> 4;

    int p = pos[b * SS + s];
    float inv = expf(-(float)(2 * j) * (9.210340371976184f / 64.f));
    float ang = (float)p * inv;
    float sn, cs;
    sincosf(ang, &sn, &cs);

    size_t base = (size_t)bh * SS * HD + (size_t)s * HD + j;
    float q1 = q[base], q2 = q[base + 32];
    float k1 = k[base], k2 = k[base + 32];
    float qa = q1 * cs - q2 * sn, qb2 = q2 * cs + q1 * sn;
    float ka = k1 * cs - k2 * sn, kb2 = k2 * cs + k1 * sn;
    __nv_bfloat16 h, l;
    split1(qa, h, l);  qh[base] = h;      ql[base] = l;
    split1(qb2, h, l); qh[base + 32] = h; ql[base + 32] = l;
    split1(ka, h, l);  kh[base] = h;      kl[base] = l;
    split1(kb2, h, l); kh[base + 32] = h; kl[base + 32] = l;
}

// ---------------- V transpose + split ----------------
__global__ __launch_bounds__(256)
void vtrans_kernel(const float* __restrict__ v,
                   __nv_bfloat16* __restrict__ vth, __nv_bfloat16* __restrict__ vtl)
{
    __shared__ float ts[64][65];
    const int tid = threadIdx.x;
    const int s0 = blockIdx.x * 64;
    const int bh = blockIdx.y;
    #pragma unroll
    for (int t = 0; t < 16; ++t) {
        int e = tid + t * 256;
        int row = e >> 6, col = e & 63;
        ts[row][col] = v[((size_t)bh * SS + s0 + row) * HD + col];
    }
    __syncthreads();
    #pragma unroll
    for (int t = 0; t < 16; ++t) {
        int e = tid + t * 256;
        int d = e >> 6, s = e & 63;
        __nv_bfloat16 h, l;
        split1(ts[s][d], h, l);
        size_t a = ((size_t)bh * HD + d) * SS + s0 + s;
        vth[a] = h;
        vtl[a] = l;
    }
}

// ---------------- attention ----------------
// smem: QH 0, QL 16384, KH 32768, KL 40960, VTH 49152, VTL 57344 (end 65536)
//       ORED reuses 32768..65536 after the loop; MKI 65536; LRED 65792; total 66816
#define A_QH   0
#define A_QL   16384
#define A_KH   32768
#define A_KL   40960
#define A_VTH  49152
#define A_VTL  57344
#define A_ORED 32768
#define A_MK   65536
#define A_LRED 65792
#define A_SMEM 66816

__global__ __launch_bounds__(256)
void attn_kernel(const __nv_bfloat16* __restrict__ qh, const __nv_bfloat16* __restrict__ ql,
                 const __nv_bfloat16* __restrict__ kh, const __nv_bfloat16* __restrict__ kl,
                 const __nv_bfloat16* __restrict__ vth, const __nv_bfloat16* __restrict__ vtl,
                 const int* __restrict__ mask,
                 float* __restrict__ qk_out,
                 __nv_bfloat16* __restrict__ ohp, __nv_bfloat16* __restrict__ olp)
{
    extern __shared__ char sm[];
    const uint32_t sb = smem_u32(sm);
    const int tid = threadIdx.x, wid = tid >> 5, l = tid & 31;
    const int wm = wid & 3, wn = wid >> 2;   // warp tile: rows wm*32, cols wn*32 of S
    const int qb = blockIdx.x;
    const int bh = blockIdx.y;
    const int b = bh >> 4, h = bh & 15;
    int* mki = (int*)(sm + A_MK);
    float* lred = (float*)(sm + A_LRED);
    float* ored = (float*)(sm + A_ORED);

    // load Q tiles (persist)
    #pragma unroll
    for (int t = 0; t < 4; ++t) {
        int e = tid + t * 256;
        int row = e >> 3, u = e & 7;
        uint32_t dst = SWZ((uint32_t)(row * 128 + u * 16));
        size_t src = ((size_t)bh * SS + qb * 128 + row) * HD + u * 8;
        *(uint4*)(sm + A_QH + dst) = *(const uint4*)(qh + src);
        *(uint4*)(sm + A_QL + dst) = *(const uint4*)(ql + src);
    }

    const int* mp = mask + b * SS;
    float* qkb = qk_out ? qk_out + ((size_t)bh * SS + (size_t)qb * 128) * SS : (float*)0;

    float oacc[2][8][4] = {};
    float lsum[2][2] = {};

    for (int kt = 0; kt < 32; ++kt) {
        if (kt > 0) __syncthreads();
        #pragma unroll
        for (int t = 0; t < 2; ++t) {
            int e = tid + t * 256;
            int row = e >> 3, u = e & 7;
            uint32_t dst = SWZ((uint32_t)(row * 128 + u * 16));
            size_t ks = ((size_t)bh * SS + kt * 64 + row) * HD + u * 8;
            size_t vs = ((size_t)bh * HD + row) * SS + kt * 64 + u * 8;
            *(uint4*)(sm + A_KH  + dst) = *(const uint4*)(kh  + ks);
            *(uint4*)(sm + A_KL  + dst) = *(const uint4*)(kl  + ks);
            *(uint4*)(sm + A_VTH + dst) = *(const uint4*)(vth + vs);
            *(uint4*)(sm + A_VTL + dst) = *(const uint4*)(vtl + vs);
        }
        if (tid < 64) mki[tid] = mp[kt * 64 + tid];
        __syncthreads();

        // ---- S = Q K^T ----
        float sacc[2][4][4] = {};
        #pragma unroll
        for (int ks = 0; ks < 4; ++ks) {
            uint32_t kh4[2][4], kl4[2][4];
            #pragma unroll
            for (int np = 0; np < 2; ++np) {
                int row = wn * 32 + np * 16 + ((l >> 4) & 1) * 8 + (l & 7);
                uint32_t off = SWZ((uint32_t)(row * 128 + ks * 32 + ((l >> 3) & 1) * 16));
                ldm4(kh4[np], sb + A_KH + off);
                ldm4(kl4[np], sb + A_KL + off);
            }
            #pragma unroll
            for (int mt = 0; mt < 2; ++mt) {
                int row = wm * 32 + mt * 16 + (l & 7) + ((l >> 3) & 1) * 8;
                uint32_t off = SWZ((uint32_t)(row * 128 + ks * 32 + ((l >> 4) & 1) * 16));
                uint32_t qh4[4], ql4[4];
                ldm4(qh4, sb + A_QH + off);
                ldm4(ql4, sb + A_QL + off);
                #pragma unroll
                for (int nt = 0; nt < 4; ++nt) {
                    const uint32_t* bhf = &kh4[nt >> 1][(nt & 1) * 2];
                    const uint32_t* blf = &kl4[nt >> 1][(nt & 1) * 2];
                    mma_bf16(sacc[mt][nt], qh4, bhf);
                    mma_bf16(sacc[mt][nt], ql4, bhf);
                    mma_bf16(sacc[mt][nt], qh4, blf);
                }
            }
        }

        // ---- mask + raw logits out + exp + pack P fragments ----
        uint32_t ph[2][2][4], pl[2][2][4];
        #pragma unroll
        for (int mt = 0; mt < 2; ++mt) {
            #pragma unroll
            for (int nt = 0; nt < 4; ++nt) {
                float* cc = sacc[mt][nt];
                int colg = wn * 32 + nt * 8 + 2 * (l & 3);
                int mv0 = mki[colg], mv1 = mki[colg + 1];
                int r0 = wm * 32 + mt * 16 + (l >> 2);
                if (qkb) {
                    float2 w0 = {mv0 ? cc[0] : NEG_INF, mv1 ? cc[1] : NEG_INF};
                    float2 w1 = {mv0 ? cc[2] : NEG_INF, mv1 ? cc[3] : NEG_INF};
                    *(float2*)(qkb + (size_t)r0 * SS + kt * 64 + colg) = w0;
                    *(float2*)(qkb + (size_t)(r0 + 8) * SS + kt * 64 + colg) = w1;
                }
                float p0 = mv0 ? __expf(cc[0]) : 0.f;
                float p1 = mv1 ? __expf(cc[1]) : 0.f;
                float p2 = mv0 ? __expf(cc[2]) : 0.f;
                float p3 = mv1 ? __expf(cc[3]) : 0.f;
                lsum[mt][0] += p0 + p1;
                lsum[mt][1] += p2 + p3;
                int t2 = nt >> 1, pos = nt & 1;
                ph[mt][t2][pos * 2]     = pk2(p0, p1);
                ph[mt][t2][pos * 2 + 1] = pk2(p2, p3);
                pl[mt][t2][pos * 2]     = pk2(p0 - bfh(p0), p1 - bfh(p1));
                pl[mt][t2][pos * 2 + 1] = pk2(p2 - bfh(p2), p3 - bfh(p3));
            }
        }

        // ---- O += P V ----
        #pragma unroll
        for (int ks = 0; ks < 2; ++ks) {
            #pragma unroll
            for (int dp = 0; dp < 4; ++dp) {
                int row = dp * 16 + ((l >> 4) & 1) * 8 + (l & 7);
                uint32_t off = SWZ((uint32_t)(row * 128 + wn * 64 + ks * 32 + ((l >> 3) & 1) * 16));
                uint32_t vh4[4], vl4[4];
                ldm4(vh4, sb + A_VTH + off);
                ldm4(vl4, sb + A_VTL + off);
                #pragma unroll
                for (int mt = 0; mt < 2; ++mt) {
                    #pragma unroll
                    for (int q2 = 0; q2 < 2; ++q2) {
                        float* o = oacc[mt][dp * 2 + q2];
                        const uint32_t* bhf = &vh4[q2 * 2];
                        const uint32_t* blf = &vl4[q2 * 2];
                        mma_bf16(o, ph[mt][ks], bhf);
                        mma_bf16(o, pl[mt][ks], bhf);
                        mma_bf16(o, ph[mt][ks], blf);
                    }
                }
            }
        }
    }
    __syncthreads();   // all PV reads done; K/V region reusable

    // ---- reduce row sums across quad lanes, publish per warp ----
    #pragma unroll
    for (int mt = 0; mt < 2; ++mt) {
        #pragma unroll
        for (int hf = 0; hf < 2; ++hf) {
            float v = lsum[mt][hf];
            v += __shfl_xor_sync(0xffffffffu, v, 1);
            v += __shfl_xor_sync(0xffffffffu, v, 2);
            int row = wm * 32 + mt * 16 + hf * 8 + (l >> 2);
            if ((l & 3) == 0) lred[wn * 128 + row] = v;
        }
    }
    // ---- wn==0 warps publish partial O ----
    if (wn == 0) {
        #pragma unroll
        for (int mt = 0; mt < 2; ++mt) {
            #pragma unroll
            for (int dt = 0; dt < 8; ++dt) {
                const float* o = oacc[mt][dt];
                int col = dt * 8 + 2 * (l & 3);
                int r0 = wm * 32 + mt * 16 + (l >> 2);
                *(float2*)(ored + (size_t)r0 * 64 + col)       = make_float2(o[0], o[1]);
                *(float2*)(ored + (size_t)(r0 + 8) * 64 + col) = make_float2(o[2], o[3]);
            }
        }
    }
    __syncthreads();

    // ---- wn==1 warps: combine, normalize, split, write ----
    if (wn == 1) {
        #pragma unroll
        for (int mt = 0; mt < 2; ++mt) {
            int r0 = wm * 32 + mt * 16 + (l >> 2);
            float lt0 = lred[r0] + lred[128 + r0];
            float lt1 = lred[r0 + 8] + lred[128 + r0 + 8];
            float inv0 = (lt0 > 0.f) ? 1.f / lt0 : 0.f;
            float inv1 = (lt1 > 0.f) ? 1.f / lt1 : 0.f;
            size_t g0 = ((size_t)b * SS + qb * 128 + r0) * DD + h * 64;
            size_t g1 = g0 + (size_t)8 * DD;
            #pragma unroll
            for (int dt = 0; dt < 8; ++dt) {
                const float* o = oacc[mt][dt];
                int col = dt * 8 + 2 * (l & 3);
                float t0 = (o[0] + ored[(size_t)r0 * 64 + col])     * inv0;
                float t1 = (o[1] + ored[(size_t)r0 * 64 + col + 1]) * inv0;
                float t2 = (o[2] + ored[(size_t)(r0+8) * 64 + col])     * inv1;
                float t3 = (o[3] + ored[(size_t)(r0+8) * 64 + col + 1]) * inv1;
                *(uint32_t*)(ohp + g0 + col) = pk2(t0, t1);
                *(uint32_t*)(olp + g0 + col) = pk2(t0 - bfh(t0), t1 - bfh(t1));
                *(uint32_t*)(ohp + g1 + col) = pk2(t2, t3);
                *(uint32_t*)(olp + g1 + col) = pk2(t2 - bfh(t2), t3 - bfh(t3));
            }
        }
    }
}

// ---------------- host ----------------
extern "C" void kernel_launch(void* const* d_in, const int* in_sizes, int n_in,
                              void* d_out, int out_size)
{
    const float* x    = (const float*)d_in[0];
    const int*   mask = (const int*)d_in[1];
    const int*   pos  = (const int*)d_in[2];
    const float* Wq = (const float*)d_in[4];
    const float* bq = (const float*)d_in[5];
    const float* Wk = (const float*)d_in[6];
    const float* Wv = (const float*)d_in[7];
    const float* bv = (const float*)d_in[8];
    const float* Wo = (const float*)d_in[9];
    const float* bo = (const float*)d_in[10];
    float* out = (float*)d_out;

    __nv_bfloat16 *xh, *xl, *wqh, *wql, *wkh, *wkl, *wvh, *wvl, *woh, *wol;
    __nv_bfloat16 *qh, *ql, *kh, *kl, *vth, *vtl, *ah, *al;
    float *qf, *kf, *vf;
    cudaGetSymbolAddress((void**)&xh, xh_d);   cudaGetSymbolAddress((void**)&xl, xl_d);
    cudaGetSymbolAddress((void**)&wqh, Wqh_d); cudaGetSymbolAddress((void**)&wql, Wql_d);
    cudaGetSymbolAddress((void**)&wkh, Wkh_d); cudaGetSymbolAddress((void**)&wkl, Wkl_d);
    cudaGetSymbolAddress((void**)&wvh, Wvh_d); cudaGetSymbolAddress((void**)&wvl, Wvl_d);
    cudaGetSymbolAddress((void**)&woh, Woh_d); cudaGetSymbolAddress((void**)&wol, Wol_d);
    cudaGetSymbolAddress((void**)&qf, qf_d);   cudaGetSymbolAddress((void**)&kf, kf_d);
    cudaGetSymbolAddress((void**)&vf, vf_d);
    cudaGetSymbolAddress((void**)&qh, qh_d);   cudaGetSymbolAddress((void**)&ql, ql_d);
    cudaGetSymbolAddress((void**)&kh, kh_d);   cudaGetSymbolAddress((void**)&kl, kl_d);
    cudaGetSymbolAddress((void**)&vth, vth_d); cudaGetSymbolAddress((void**)&vtl, vtl_d);
    cudaGetSymbolAddress((void**)&ah, oh_d);   cudaGetSymbolAddress((void**)&al, ol_d);

    const long long OUTE = (long long)BB * SS * DD;
    const long long QKE  = (long long)BB * HH * SS * SS;
    float* qkp = ((long long)out_size >= OUTE + QKE) ? out + OUTE : (float*)0;

    const float SC = 0.35355339059327373f;   // 64^-0.25

    split_kernel<<<(BB*SS*DD/4 + 255)/256, 256>>>(x, xh, xl, BB*SS*DD/4);
    split_kernel<<<(DD*DD/4 + 255)/256, 256>>>(Wq, wqh, wql, DD*DD/4);
    split_kernel<<<(DD*DD/4 + 255)/256, 256>>>(Wk, wkh, wkl, DD*DD/4);
    split_kernel<<<(DD*DD/4 + 255)/256, 256>>>(Wv, wvh, wvl, DD*DD/4);
    split_kernel<<<(DD*DD/4 + 255)/256, 256>>>(Wo, woh, wol, DD*DD/4);

    cudaFuncSetAttribute(bgemm<true>,  cudaFuncAttributeMaxDynamicSharedMemorySize, G_SMEM);
    cudaFuncSetAttribute(bgemm<false>, cudaFuncAttributeMaxDynamicSharedMemorySize, G_SMEM);
    cudaFuncSetAttribute(attn_kernel,  cudaFuncAttributeMaxDynamicSharedMemorySize, A_SMEM);

    dim3 gg(DD / 128, (BB * SS) / 128);
    bgemm<true><<<gg, 256, G_SMEM>>>(xh, xl, wqh, wql, bq, SC, qf);
    bgemm<true><<<gg, 256, G_SMEM>>>(xh, xl, wkh, wkl, (const float*)0, SC, kf);
    bgemm<true><<<gg, 256, G_SMEM>>>(xh, xl, wvh, wvl, bv, 1.f, vf);

    rope_kernel<<<(BB*HH*SS*32)/256, 256>>>(qf, kf, pos, qh, ql, kh, kl);
    vtrans_kernel<<<dim3(SS/64, BB*HH), 256>>>(vf, vth, vtl);

    attn_kernel<<<dim3(SS/128, BB*HH), 256, A_SMEM>>>(qh, ql, kh, kl, vth, vtl,
                                                      mask, qkp, ah, al);

    bgemm<false><<<gg, 256, G_SMEM>>>(ah, al, woh, wol, bo, 1.f, out);
}

// round 11
// speedup vs baseline: 3.0856x; 1.3422x over previous
#include <cuda_runtime.h>
#include <cuda_bf16.h>
#include <stdint.h>
#include <math.h>

#define BB 2
#define SS 2048
#define DD 1024
#define HH 16
#define HD 64
#define NEG_INF (__int_as_float(0xff800000))

// ---------------- device scratch ----------------
__device__ __nv_bfloat16 xh_d[BB*SS*DD], xl_d[BB*SS*DD];
__device__ __nv_bfloat16 Wqh_d[DD*DD], Wql_d[DD*DD];
__device__ __nv_bfloat16 Wkh_d[DD*DD], Wkl_d[DD*DD];
__device__ __nv_bfloat16 Wvh_d[DD*DD], Wvl_d[DD*DD];
__device__ __nv_bfloat16 Woh_d[DD*DD], Wol_d[DD*DD];
__device__ float qf_d[BB*HH*SS*HD], kf_d[BB*HH*SS*HD], vf_d[BB*HH*SS*HD];
__device__ __nv_bfloat16 qh_d[BB*HH*SS*HD], ql_d[BB*HH*SS*HD];
__device__ __nv_bfloat16 kh_d[BB*HH*SS*HD], kl_d[BB*HH*SS*HD];
__device__ __nv_bfloat16 vth_d[BB*HH*SS*HD], vtl_d[BB*HH*SS*HD];
__device__ __nv_bfloat16 oh_d[BB*SS*DD], ol_d[BB*SS*DD];

// ---------------- helpers ----------------
__device__ __forceinline__ uint32_t smem_u32(const void* p) {
    uint32_t a;
    asm("{ .reg .u64 t; cvta.to.shared.u64 t, %1; cvt.u32.u64 %0, t; }" : "=r"(a) : "l"(p));
    return a;
}
#define SWZ(x) ((x) ^ (((x) >> 3) & 0x70))

__device__ __forceinline__ void cpa16(uint32_t dst, const void* src) {
    asm volatile("cp.async.cg.shared.global [%0], [%1], 16;" :: "r"(dst), "l"(src));
}
#define CP_COMMIT() asm volatile("cp.async.commit_group;" ::: "memory")
#define CP_WAIT1()  asm volatile("cp.async.wait_group 1;" ::: "memory")
#define CP_WAIT0()  asm volatile("cp.async.wait_group 0;" ::: "memory")

__device__ __forceinline__ void ldm4(uint32_t r[4], uint32_t a) {
    asm volatile("ldmatrix.sync.aligned.m8n8.x4.shared.b16 {%0,%1,%2,%3}, [%4];"
        : "=r"(r[0]), "=r"(r[1]), "=r"(r[2]), "=r"(r[3]) : "r"(a));
}
__device__ __forceinline__ void mma_bf16(float* c, const uint32_t* a, const uint32_t* b) {
    asm volatile("mma.sync.aligned.m16n8k16.row.col.f32.bf16.bf16.f32 "
        "{%0,%1,%2,%3}, {%4,%5,%6,%7}, {%8,%9}, {%0,%1,%2,%3};"
        : "+f"(c[0]), "+f"(c[1]), "+f"(c[2]), "+f"(c[3])
        : "r"(a[0]), "r"(a[1]), "r"(a[2]), "r"(a[3]), "r"(b[0]), "r"(b[1]));
}
__device__ __forceinline__ uint32_t pk2(float a, float b) {
    __nv_bfloat162 t = __floats2bfloat162_rn(a, b);
    return *(uint32_t*)&t;
}
__device__ __forceinline__ float bfh(float v) {
    return __bfloat162float(__float2bfloat16_rn(v));
}
__device__ __forceinline__ void split1(float v, __nv_bfloat16& h, __nv_bfloat16& l) {
    h = __float2bfloat16_rn(v);
    l = __float2bfloat16_rn(v - __bfloat162float(h));
}

// ---------------- split kernel ----------------
__global__ void split_kernel(const float* __restrict__ in,
                             __nv_bfloat16* __restrict__ oh,
                             __nv_bfloat16* __restrict__ ol, int n4) {
    int i = blockIdx.x * blockDim.x + threadIdx.x;
    if (i >= n4) return;
    float4 v = ((const float4*)in)[i];
    uint2 hv, lv;
    hv.x = pk2(v.x, v.y); hv.y = pk2(v.z, v.w);
    lv.x = pk2(v.x - bfh(v.x), v.y - bfh(v.y));
    lv.y = pk2(v.z - bfh(v.z), v.w - bfh(v.w));
    ((uint2*)oh)[i] = hv;
    ((uint2*)ol)[i] = lv;
}

// ---------------- split-bf16 HMMA GEMM, 2-stage cp.async pipeline ----------------
// tile 128x128, K-chunk 64, 256 thr, 8 warps (2m x 4n), warp tile 64x32.
// stage layout (within 65536B stage): AH 0, AL 16384, BH 32768, BL 49152
#define G_STG 65536
#define G_SMEM 131072

template<bool HEAD>
__global__ __launch_bounds__(256, 1)
void bgemm(const __nv_bfloat16* __restrict__ Ah, const __nv_bfloat16* __restrict__ Al,
           const __nv_bfloat16* __restrict__ Bh, const __nv_bfloat16* __restrict__ Bl,
           const float* __restrict__ bias, float scale, float* __restrict__ C)
{
    extern __shared__ char sm[];
    const uint32_t sb = smem_u32(sm);
    const int tid = threadIdx.x, wid = tid >> 5, l = tid & 31;
    const int wm = wid & 1, wn = wid >> 1;
    const int m0 = blockIdx.y * 128, n0 = blockIdx.x * 128;

    float acc[4][4][4] = {};

    auto load_stage = [&](int c, int buf) {
        const int kt = c * 64;
        const uint32_t so = sb + buf * G_STG;
        #pragma unroll
        for (int t = 0; t < 4; ++t) {
            int e = tid + t * 256;
            int row = e >> 3, u = e & 7;
            uint32_t dst = SWZ((uint32_t)(row * 128 + u * 16));
            size_t ga = (size_t)(m0 + row) * DD + kt + u * 8;
            size_t gb = (size_t)(n0 + row) * DD + kt + u * 8;
            cpa16(so + dst,         Ah + ga);
            cpa16(so + 16384 + dst, Al + ga);
            cpa16(so + 32768 + dst, Bh + gb);
            cpa16(so + 49152 + dst, Bl + gb);
        }
    };

    load_stage(0, 0);
    CP_COMMIT();

    for (int c = 0; c < 16; ++c) {
        if (c < 15) { load_stage(c + 1, (c + 1) & 1); CP_COMMIT(); CP_WAIT1(); }
        else        { CP_WAIT0(); }
        __syncthreads();
        const uint32_t so = sb + (c & 1) * G_STG;
        #pragma unroll
        for (int ks = 0; ks < 4; ++ks) {
            uint32_t bh4[2][4], bl4[2][4];
            #pragma unroll
            for (int np = 0; np < 2; ++np) {
                int row = wn * 32 + np * 16 + ((l >> 4) & 1) * 8 + (l & 7);
                uint32_t off = SWZ((uint32_t)(row * 128 + ks * 32 + ((l >> 3) & 1) * 16));
                ldm4(bh4[np], so + 32768 + off);
                ldm4(bl4[np], so + 49152 + off);
            }
            #pragma unroll
            for (int mt = 0; mt < 4; ++mt) {
                int row = wm * 64 + mt * 16 + (l & 7) + ((l >> 3) & 1) * 8;
                uint32_t off = SWZ((uint32_t)(row * 128 + ks * 32 + ((l >> 4) & 1) * 16));
                uint32_t ah4[4], al4[4];
                ldm4(ah4, so + off);
                ldm4(al4, so + 16384 + off);
                #pragma unroll
                for (int nt = 0; nt < 4; ++nt) {
                    const uint32_t* bh = &bh4[nt >> 1][(nt & 1) * 2];
                    const uint32_t* bl = &bl4[nt >> 1][(nt & 1) * 2];
                    mma_bf16(acc[mt][nt], ah4, bh);
                    mma_bf16(acc[mt][nt], al4, bh);
                    mma_bf16(acc[mt][nt], ah4, bl);
                }
            }
        }
        __syncthreads();
    }

    #pragma unroll
    for (int mt = 0; mt < 4; ++mt) {
        #pragma unroll
        for (int nt = 0; nt < 4; ++nt) {
            const float* cc = acc[mt][nt];
            int col = n0 + wn * 32 + nt * 8 + 2 * (l & 3);
            float b0 = bias ? bias[col] : 0.f;
            float b1 = bias ? bias[col + 1] : 0.f;
            int r0 = m0 + wm * 64 + mt * 16 + (l >> 2);
            #pragma unroll
            for (int hh = 0; hh < 2; ++hh) {
                int r = r0 + hh * 8;
                float2 w = {(cc[hh*2] + b0) * scale, (cc[hh*2+1] + b1) * scale};
                if (HEAD) {
                    int bb = r >> 11, s = r & (SS - 1);
                    int h = col >> 6, d = col & 63;
                    *(float2*)(C + (((size_t)(bb * HH + h)) * SS + s) * HD + d) = w;
                } else {
                    *(float2*)(C + (size_t)r * DD + col) = w;
                }
            }
        }
    }
}

// ---------------- RoPE + split ----------------
__global__ void rope_kernel(const float* __restrict__ q, const float* __restrict__ k,
                            const int* __restrict__ pos,
                            __nv_bfloat16* __restrict__ qh, __nv_bfloat16* __restrict__ ql,
                            __nv_bfloat16* __restrict__ kh, __nv_bfloat16* __restrict__ kl)
{
    int idx = blockIdx.x * blockDim.x + threadIdx.x;
    if (idx >= BB * HH * SS * 32) return;
    int j = idx & 31;
    int s = (idx >> 5) & (SS - 1);
    int bh = idx >> 16;
    int b = bh >> 4;

    int p = pos[b * SS + s];
    float inv = expf(-(float)(2 * j) * (9.210340371976184f / 64.f));
    float ang = (float)p * inv;
    float sn, cs;
    sincosf(ang, &sn, &cs);

    size_t base = (size_t)bh * SS * HD + (size_t)s * HD + j;
    float q1 = q[base], q2 = q[base + 32];
    float k1 = k[base], k2 = k[base + 32];
    float qa = q1 * cs - q2 * sn, qb2 = q2 * cs + q1 * sn;
    float ka = k1 * cs - k2 * sn, kb2 = k2 * cs + k1 * sn;
    __nv_bfloat16 h, l;
    split1(qa, h, l);  qh[base] = h;      ql[base] = l;
    split1(qb2, h, l); qh[base + 32] = h; ql[base + 32] = l;
    split1(ka, h, l);  kh[base] = h;      kl[base] = l;
    split1(kb2, h, l); kh[base + 32] = h; kl[base + 32] = l;
}

// ---------------- V transpose + split ----------------
__global__ __launch_bounds__(256)
void vtrans_kernel(const float* __restrict__ v,
                   __nv_bfloat16* __restrict__ vth, __nv_bfloat16* __restrict__ vtl)
{
    __shared__ float ts[64][65];
    const int tid = threadIdx.x;
    const int s0 = blockIdx.x * 64;
    const int bh = blockIdx.y;
    #pragma unroll
    for (int t = 0; t < 16; ++t) {
        int e = tid + t * 256;
        int row = e >> 6, col = e & 63;
        ts[row][col] = v[((size_t)bh * SS + s0 + row) * HD + col];
    }
    __syncthreads();
    #pragma unroll
    for (int t = 0; t < 16; ++t) {
        int e = tid + t * 256;
        int d = e >> 6, s = e & 63;
        __nv_bfloat16 h, l;
        split1(ts[s][d], h, l);
        size_t a = ((size_t)bh * HD + d) * SS + s0 + s;
        vth[a] = h;
        vtl[a] = l;
    }
}

// ---------------- attention, 2-stage cp.async pipeline on K/V ----------------
// smem: QH 0, QL 16384 | stages at 32768 (stride 32768): KH 0, KL 8192, VTH 16384, VTL 24576
// ORED reuses 32768..65536 after loop | MKI 98304 (2x64 ints) | LRED 98816 (1KB) | total 99840
#define A_QH   0
#define A_QL   16384
#define A_ST   32768
#define A_STG  32768
#define A_ORED 32768
#define A_MK   98304
#define A_LRED 98816
#define A_SMEM 99840

__global__ __launch_bounds__(256, 2)
void attn_kernel(const __nv_bfloat16* __restrict__ qh, const __nv_bfloat16* __restrict__ ql,
                 const __nv_bfloat16* __restrict__ kh, const __nv_bfloat16* __restrict__ kl,
                 const __nv_bfloat16* __restrict__ vth, const __nv_bfloat16* __restrict__ vtl,
                 const int* __restrict__ mask,
                 float* __restrict__ qk_out,
                 __nv_bfloat16* __restrict__ ohp, __nv_bfloat16* __restrict__ olp)
{
    extern __shared__ char sm[];
    const uint32_t sb = smem_u32(sm);
    const int tid = threadIdx.x, wid = tid >> 5, l = tid & 31;
    const int wm = wid & 3, wn = wid >> 2;
    const int qb = blockIdx.x;
    const int bh = blockIdx.y;
    const int b = bh >> 4, h = bh & 15;
    int* mki = (int*)(sm + A_MK);
    float* lred = (float*)(sm + A_LRED);
    float* ored = (float*)(sm + A_ORED);

    // load Q tiles (persist)
    #pragma unroll
    for (int t = 0; t < 4; ++t) {
        int e = tid + t * 256;
        int row = e >> 3, u = e & 7;
        uint32_t dst = SWZ((uint32_t)(row * 128 + u * 16));
        size_t src = ((size_t)bh * SS + qb * 128 + row) * HD + u * 8;
        *(uint4*)(sm + A_QH + dst) = *(const uint4*)(qh + src);
        *(uint4*)(sm + A_QL + dst) = *(const uint4*)(ql + src);
    }

    const int* mp = mask + b * SS;
    float* qkb = qk_out ? qk_out + ((size_t)bh * SS + (size_t)qb * 128) * SS : (float*)0;

    auto load_kv = [&](int kt, int buf) {
        const uint32_t so = sb + A_ST + buf * A_STG;
        #pragma unroll
        for (int t = 0; t < 2; ++t) {
            int e = tid + t * 256;
            int row = e >> 3, u = e & 7;
            uint32_t dst = SWZ((uint32_t)(row * 128 + u * 16));
            size_t ks = ((size_t)bh * SS + kt * 64 + row) * HD + u * 8;
            size_t vs = ((size_t)bh * HD + row) * SS + kt * 64 + u * 8;
            cpa16(so + dst,         kh  + ks);
            cpa16(so + 8192 + dst,  kl  + ks);
            cpa16(so + 16384 + dst, vth + vs);
            cpa16(so + 24576 + dst, vtl + vs);
        }
        if (tid < 16) cpa16(sb + A_MK + buf * 256 + tid * 16, mp + kt * 64 + tid * 4);
    };

    float oacc[2][8][4] = {};
    float lsum[2][2] = {};

    load_kv(0, 0);
    CP_COMMIT();

    for (int kt = 0; kt < 32; ++kt) {
        if (kt < 31) { load_kv(kt + 1, (kt + 1) & 1); CP_COMMIT(); CP_WAIT1(); }
        else         { CP_WAIT0(); }
        __syncthreads();
        const uint32_t so = sb + A_ST + (kt & 1) * A_STG;
        const int* mk = mki + (kt & 1) * 64;

        // ---- S = Q K^T ----
        float sacc[2][4][4] = {};
        #pragma unroll
        for (int ks = 0; ks < 4; ++ks) {
            uint32_t kh4[2][4], kl4[2][4];
            #pragma unroll
            for (int np = 0; np < 2; ++np) {
                int row = wn * 32 + np * 16 + ((l >> 4) & 1) * 8 + (l & 7);
                uint32_t off = SWZ((uint32_t)(row * 128 + ks * 32 + ((l >> 3) & 1) * 16));
                ldm4(kh4[np], so + off);
                ldm4(kl4[np], so + 8192 + off);
            }
            #pragma unroll
            for (int mt = 0; mt < 2; ++mt) {
                int row = wm * 32 + mt * 16 + (l & 7) + ((l >> 3) & 1) * 8;
                uint32_t off = SWZ((uint32_t)(row * 128 + ks * 32 + ((l >> 4) & 1) * 16));
                uint32_t qh4[4], ql4[4];
                ldm4(qh4, sb + A_QH + off);
                ldm4(ql4, sb + A_QL + off);
                #pragma unroll
                for (int nt = 0; nt < 4; ++nt) {
                    const uint32_t* bhf = &kh4[nt >> 1][(nt & 1) * 2];
                    const uint32_t* blf = &kl4[nt >> 1][(nt & 1) * 2];
                    mma_bf16(sacc[mt][nt], qh4, bhf);
                    mma_bf16(sacc[mt][nt], ql4, bhf);
                    mma_bf16(sacc[mt][nt], qh4, blf);
                }
            }
        }

        // ---- mask + raw logits out + exp + pack P fragments ----
        uint32_t ph[2][2][4], pl[2][2][4];
        #pragma unroll
        for (int mt = 0; mt < 2; ++mt) {
            #pragma unroll
            for (int nt = 0; nt < 4; ++nt) {
                float* cc = sacc[mt][nt];
                int colg = wn * 32 + nt * 8 + 2 * (l & 3);
                int mv0 = mk[colg], mv1 = mk[colg + 1];
                int r0 = wm * 32 + mt * 16 + (l >> 2);
                if (qkb) {
                    float2 w0 = {mv0 ? cc[0] : NEG_INF, mv1 ? cc[1] : NEG_INF};
                    float2 w1 = {mv0 ? cc[2] : NEG_INF, mv1 ? cc[3] : NEG_INF};
                    __stcs((float2*)(qkb + (size_t)r0 * SS + kt * 64 + colg), w0);
                    __stcs((float2*)(qkb + (size_t)(r0 + 8) * SS + kt * 64 + colg), w1);
                }
                float p0 = mv0 ? __expf(cc[0]) : 0.f;
                float p1 = mv1 ? __expf(cc[1]) : 0.f;
                float p2 = mv0 ? __expf(cc[2]) : 0.f;
                float p3 = mv1 ? __expf(cc[3]) : 0.f;
                lsum[mt][0] += p0 + p1;
                lsum[mt][1] += p2 + p3;
                int t2 = nt >> 1, pos = nt & 1;
                ph[mt][t2][pos * 2]     = pk2(p0, p1);
                ph[mt][t2][pos * 2 + 1] = pk2(p2, p3);
                pl[mt][t2][pos * 2]     = pk2(p0 - bfh(p0), p1 - bfh(p1));
                pl[mt][t2][pos * 2 + 1] = pk2(p2 - bfh(p2), p3 - bfh(p3));
            }
        }

        // ---- O += P V ----
        #pragma unroll
        for (int ks = 0; ks < 2; ++ks) {
            #pragma unroll
            for (int dp = 0; dp < 4; ++dp) {
                int row = dp * 16 + ((l >> 4) & 1) * 8 + (l & 7);
                uint32_t off = SWZ((uint32_t)(row * 128 + wn * 64 + ks * 32 + ((l >> 3) & 1) * 16));
                uint32_t vh4[4], vl4[4];
                ldm4(vh4, so + 16384 + off);
                ldm4(vl4, so + 24576 + off);
                #pragma unroll
                for (int mt = 0; mt < 2; ++mt) {
                    #pragma unroll
                    for (int q2 = 0; q2 < 2; ++q2) {
                        float* o = oacc[mt][dp * 2 + q2];
                        const uint32_t* bhf = &vh4[q2 * 2];
                        const uint32_t* blf = &vl4[q2 * 2];
                        mma_bf16(o, ph[mt][ks], bhf);
                        mma_bf16(o, pl[mt][ks], bhf);
                        mma_bf16(o, ph[mt][ks], blf);
                    }
                }
            }
        }
        __syncthreads();
    }

    // ---- reduce row sums across quad lanes, publish per warp ----
    #pragma unroll
    for (int mt = 0; mt < 2; ++mt) {
        #pragma unroll
        for (int hf = 0; hf < 2; ++hf) {
            float v = lsum[mt][hf];
            v += __shfl_xor_sync(0xffffffffu, v, 1);
            v += __shfl_xor_sync(0xffffffffu, v, 2);
            int row = wm * 32 + mt * 16 + hf * 8 + (l >> 2);
            if ((l & 3) == 0) lred[wn * 128 + row] = v;
        }
    }
    // ---- wn==0 warps publish partial O (reuses stage-0 region) ----
    if (wn == 0) {
        #pragma unroll
        for (int mt = 0; mt < 2; ++mt) {
            #pragma unroll
            for (int dt = 0; dt < 8; ++dt) {
                const float* o = oacc[mt][dt];
                int col = dt * 8 + 2 * (l & 3);
                int r0 = wm * 32 + mt * 16 + (l >> 2);
                *(float2*)(ored + (size_t)r0 * 64 + col)       = make_float2(o[0], o[1]);
                *(float2*)(ored + (size_t)(r0 + 8) * 64 + col) = make_float2(o[2], o[3]);
            }
        }
    }
    __syncthreads();

    // ---- wn==1 warps: combine, normalize, split, write ----
    if (wn == 1) {
        #pragma unroll
        for (int mt = 0; mt < 2; ++mt) {
            int r0 = wm * 32 + mt * 16 + (l >> 2);
            float lt0 = lred[r0] + lred[128 + r0];
            float lt1 = lred[r0 + 8] + lred[128 + r0 + 8];
            float inv0 = (lt0 > 0.f) ? 1.f / lt0 : 0.f;
            float inv1 = (lt1 > 0.f) ? 1.f / lt1 : 0.f;
            size_t g0 = ((size_t)b * SS + qb * 128 + r0) * DD + h * 64;
            size_t g1 = g0 + (size_t)8 * DD;
            #pragma unroll
            for (int dt = 0; dt < 8; ++dt) {
                const float* o = oacc[mt][dt];
                int col = dt * 8 + 2 * (l & 3);
                float t0 = (o[0] + ored[(size_t)r0 * 64 + col])     * inv0;
                float t1 = (o[1] + ored[(size_t)r0 * 64 + col + 1]) * inv0;
                float t2 = (o[2] + ored[(size_t)(r0+8) * 64 + col])     * inv1;
                float t3 = (o[3] + ored[(size_t)(r0+8) * 64 + col + 1]) * inv1;
                *(uint32_t*)(ohp + g0 + col) = pk2(t0, t1);
                *(uint32_t*)(olp + g0 + col) = pk2(t0 - bfh(t0), t1 - bfh(t1));
                *(uint32_t*)(ohp + g1 + col) = pk2(t2, t3);
                *(uint32_t*)(olp + g1 + col) = pk2(t2 - bfh(t2), t3 - bfh(t3));
            }
        }
    }
}

// ---------------- host ----------------
extern "C" void kernel_launch(void* const* d_in, const int* in_sizes, int n_in,
                              void* d_out, int out_size)
{
    const float* x    = (const float*)d_in[0];
    const int*   mask = (const int*)d_in[1];
    const int*   pos  = (const int*)d_in[2];
    const float* Wq = (const float*)d_in[4];
    const float* bq = (const float*)d_in[5];
    const float* Wk = (const float*)d_in[6];
    const float* Wv = (const float*)d_in[7];
    const float* bv = (const float*)d_in[8];
    const float* Wo = (const float*)d_in[9];
    const float* bo = (const float*)d_in[10];
    float* out = (float*)d_out;

    __nv_bfloat16 *xh, *xl, *wqh, *wql, *wkh, *wkl, *wvh, *wvl, *woh, *wol;
    __nv_bfloat16 *qh, *ql, *kh, *kl, *vth, *vtl, *ah, *al;
    float *qf, *kf, *vf;
    cudaGetSymbolAddress((void**)&xh, xh_d);   cudaGetSymbolAddress((void**)&xl, xl_d);
    cudaGetSymbolAddress((void**)&wqh, Wqh_d); cudaGetSymbolAddress((void**)&wql, Wql_d);
    cudaGetSymbolAddress((void**)&wkh, Wkh_d); cudaGetSymbolAddress((void**)&wkl, Wkl_d);
    cudaGetSymbolAddress((void**)&wvh, Wvh_d); cudaGetSymbolAddress((void**)&wvl, Wvl_d);
    cudaGetSymbolAddress((void**)&woh, Woh_d); cudaGetSymbolAddress((void**)&wol, Wol_d);
    cudaGetSymbolAddress((void**)&qf, qf_d);   cudaGetSymbolAddress((void**)&kf, kf_d);
    cudaGetSymbolAddress((void**)&vf, vf_d);
    cudaGetSymbolAddress((void**)&qh, qh_d);   cudaGetSymbolAddress((void**)&ql, ql_d);
    cudaGetSymbolAddress((void**)&kh, kh_d);   cudaGetSymbolAddress((void**)&kl, kl_d);
    cudaGetSymbolAddress((void**)&vth, vth_d); cudaGetSymbolAddress((void**)&vtl, vtl_d);
    cudaGetSymbolAddress((void**)&ah, oh_d);   cudaGetSymbolAddress((void**)&al, ol_d);

    const long long OUTE = (long long)BB * SS * DD;
    const long long QKE  = (long long)BB * HH * SS * SS;
    float* qkp = ((long long)out_size >= OUTE + QKE) ? out + OUTE : (float*)0;

    const float SC = 0.35355339059327373f;   // 64^-0.25

    split_kernel<<<(BB*SS*DD/4 + 255)/256, 256>>>(x, xh, xl, BB*SS*DD/4);
    split_kernel<<<(DD*DD/4 + 255)/256, 256>>>(Wq, wqh, wql, DD*DD/4);
    split_kernel<<<(DD*DD/4 + 255)/256, 256>>>(Wk, wkh, wkl, DD*DD/4);
    split_kernel<<<(DD*DD/4 + 255)/256, 256>>>(Wv, wvh, wvl, DD*DD/4);
    split_kernel<<<(DD*DD/4 + 255)/256, 256>>>(Wo, woh, wol, DD*DD/4);

    cudaFuncSetAttribute(bgemm<true>,  cudaFuncAttributeMaxDynamicSharedMemorySize, G_SMEM);
    cudaFuncSetAttribute(bgemm<false>, cudaFuncAttributeMaxDynamicSharedMemorySize, G_SMEM);
    cudaFuncSetAttribute(attn_kernel,  cudaFuncAttributeMaxDynamicSharedMemorySize, A_SMEM);

    dim3 gg(DD / 128, (BB * SS) / 128);
    bgemm<true><<<gg, 256, G_SMEM>>>(xh, xl, wqh, wql, bq, SC, qf);
    bgemm<true><<<gg, 256, G_SMEM>>>(xh, xl, wkh, wkl, (const float*)0, SC, kf);
    bgemm<true><<<gg, 256, G_SMEM>>>(xh, xl, wvh, wvl, bv, 1.f, vf);

    rope_kernel<<<(BB*HH*SS*32)/256, 256>>>(qf, kf, pos, qh, ql, kh, kl);
    vtrans_kernel<<<dim3(SS/64, BB*HH), 256>>>(vf, vth, vtl);

    attn_kernel<<<dim3(SS/128, BB*HH), 256, A_SMEM>>>(qh, ql, kh, kl, vth, vtl,
                                                      mask, qkp, ah, al);

    bgemm<false><<<gg, 256, G_SMEM>>>(ah, al, woh, wol, bo, 1.f, out);
}